// round 10
// baseline (speedup 1.0000x reference)
#include <cuda_runtime.h>
#include <cuda_bf16.h>

#define N_NODES 20000
#define N_EDGES 640000
#define HIDDEN  128
#define KDIM    256   // concat [agg | x]

#define SCAN_NB    80
#define SCAN_CHUNK 250   // 80 * 250 = 20000 exactly

// ---------------- scratch (device globals; 16B-aligned) --------------------
__device__ __align__(16) float g_agg[N_NODES * HIDDEN];
__device__ __align__(16) float g_Wt[KDIM * HIDDEN];          // Wt[k][j]
__device__ int g_cnt[N_NODES];
__device__ int g_blocksum[SCAN_NB];
__device__ int g_rowstart[N_NODES + 1];
__device__ int g_wofs[N_NODES];
__device__ int g_srcidx[N_EDGES];
__device__ int g_is64;

__device__ __forceinline__ int load_idx(const void* ei, int pos) {
    if (g_is64) return (int)((const long long*)ei)[pos];
    return ((const int*)ei)[pos];
}

// ---------------- kernel 1: detect dtype + build Wt + zero counters --------
__global__ void init_kernel(const float* __restrict__ Wl,
                            const float* __restrict__ Wr,
                            const int* __restrict__ ei_raw) {
    int i = blockIdx.x * blockDim.x + threadIdx.x;
    if (i == 0) {
        // int64 ids < 20000 => every odd 32-bit word is zero
        int ok64 = 1;
#pragma unroll 1
        for (int k = 1; k < 256; k += 2) ok64 &= (ei_raw[k] == 0);
        g_is64 = ok64;
    }
    if (i < KDIM * HIDDEN) {
        int k = i >> 7;
        int j = i & 127;
        g_Wt[i] = (k < HIDDEN) ? Wl[j * HIDDEN + k]
                               : Wr[j * HIDDEN + (k - HIDDEN)];
    }
    if (i < N_NODES) g_cnt[i] = 0;
}

// ---------------- kernel 2: histogram of dst ------------------------------
__global__ void hist_kernel(const void* __restrict__ ei) {
    int e = blockIdx.x * blockDim.x + threadIdx.x;
    if (e >= N_EDGES) return;
    int d = load_idx(ei, N_EDGES + e);
    if ((unsigned)d < N_NODES) atomicAdd(&g_cnt[d], 1);
}

// ---------------- kernel 3a: per-block partial sums ------------------------
__global__ __launch_bounds__(256)
void partial_kernel() {
    __shared__ int sh[256];
    int t = threadIdx.x, b = blockIdx.x;
    int v = (t < SCAN_CHUNK) ? g_cnt[b * SCAN_CHUNK + t] : 0;
    sh[t] = v;
    __syncthreads();
#pragma unroll
    for (int o = 128; o > 0; o >>= 1) {
        if (t < o) sh[t] += sh[t + o];
        __syncthreads();
    }
    if (t == 0) g_blocksum[b] = sh[0];
}

// ---------------- kernel 3b: apply scan (exclusive offsets) ----------------
__global__ __launch_bounds__(256)
void apply_kernel() {
    __shared__ int sh[256];
    __shared__ int base_sh;
    int t = threadIdx.x, b = blockIdx.x;

    // base = sum of blocksums of preceding blocks
    sh[t] = (t < b) ? g_blocksum[t] : 0;
    __syncthreads();
#pragma unroll
    for (int o = 128; o > 0; o >>= 1) {
        if (t < o) sh[t] += sh[t + o];
        __syncthreads();
    }
    if (t == 0) base_sh = sh[0];
    __syncthreads();
    int base = base_sh;

    int idx = b * SCAN_CHUNK + t;
    int v = (t < SCAN_CHUNK) ? g_cnt[idx] : 0;
    sh[t] = v;
    __syncthreads();
    // Hillis-Steele inclusive scan over 256
#pragma unroll
    for (int o = 1; o < 256; o <<= 1) {
        int x = sh[t];
        int add = (t >= o) ? sh[t - o] : 0;
        __syncthreads();
        sh[t] = x + add;
        __syncthreads();
    }
    int excl = base + sh[t] - v;
    if (t < SCAN_CHUNK) {
        g_rowstart[idx] = excl;
        g_wofs[idx]     = excl;
    }
    if (b == SCAN_NB - 1 && t == SCAN_CHUNK - 1)
        g_rowstart[N_NODES] = excl + v;
}

// ---------------- kernel 4: place src into CSR -----------------------------
__global__ void place_kernel(const void* __restrict__ ei) {
    int e = blockIdx.x * blockDim.x + threadIdx.x;
    if (e >= N_EDGES) return;
    int s = load_idx(ei, e);
    int d = load_idx(ei, N_EDGES + e);
    if ((unsigned)s >= N_NODES || (unsigned)d >= N_NODES) return;
    int pos = atomicAdd(&g_wofs[d], 1);
    g_srcidx[pos] = s;
}

// ---------------- kernel 5: atomic-free gather + mean ----------------------
__global__ void gather_kernel(const float* __restrict__ feat) {
    int gtid = blockIdx.x * blockDim.x + threadIdx.x;
    int nid  = gtid >> 5;
    int lane = gtid & 31;
    if (nid >= N_NODES) return;

    int beg = g_rowstart[nid];
    int end = g_rowstart[nid + 1];

    float4 acc = make_float4(0.f, 0.f, 0.f, 0.f);
    int i = beg;
#pragma unroll 1
    for (; i + 4 <= end; i += 4) {
        int s0 = g_srcidx[i + 0];
        int s1 = g_srcidx[i + 1];
        int s2 = g_srcidx[i + 2];
        int s3 = g_srcidx[i + 3];
        float4 v0 = *reinterpret_cast<const float4*>(&feat[s0 * HIDDEN + lane * 4]);
        float4 v1 = *reinterpret_cast<const float4*>(&feat[s1 * HIDDEN + lane * 4]);
        float4 v2 = *reinterpret_cast<const float4*>(&feat[s2 * HIDDEN + lane * 4]);
        float4 v3 = *reinterpret_cast<const float4*>(&feat[s3 * HIDDEN + lane * 4]);
        acc.x += v0.x + v1.x + v2.x + v3.x;
        acc.y += v0.y + v1.y + v2.y + v3.y;
        acc.z += v0.z + v1.z + v2.z + v3.z;
        acc.w += v0.w + v1.w + v2.w + v3.w;
    }
#pragma unroll 1
    for (; i < end; i++) {
        int s = g_srcidx[i];
        float4 v = *reinterpret_cast<const float4*>(&feat[s * HIDDEN + lane * 4]);
        acc.x += v.x; acc.y += v.y; acc.z += v.z; acc.w += v.w;
    }
    int deg = end - beg;
    float inv = 1.0f / (float)max(deg, 1);
    acc.x *= inv; acc.y *= inv; acc.z *= inv; acc.w *= inv;
    *reinterpret_cast<float4*>(&g_agg[nid * HIDDEN + lane * 4]) = acc;
}

// ---------------- kernel 6: fused SGEMM (512 threads, padded smem) ---------
// out[m][j] = sum_k A[m][k] * Wt[k][j] + b[j],  A = [agg | feat]
#define BM 128
#define BN 128
#define BK 32
#define TM 4
#define TN 8
#define GT 512

__global__ __launch_bounds__(GT)
void gemm_kernel(const float* __restrict__ feat,
                 const float* __restrict__ bias,
                 float* __restrict__ out) {
    __shared__ float As[BM][BK + 1];   // pad: conflict-free col reads
    __shared__ float Bs[BK][BN];

    const int tid     = threadIdx.x;
    const int block_m = blockIdx.x * BM;
    const int trow    = tid / 16;  // 0..31
    const int tcol    = tid % 16;  // 0..15

    float acc[TM][TN];
#pragma unroll
    for (int i = 0; i < TM; i++)
#pragma unroll
        for (int j = 0; j < TN; j++) acc[i][j] = 0.0f;

    float bfrag[TN];
#pragma unroll
    for (int j = 0; j < TN; j++) bfrag[j] = __ldg(&bias[tcol * TN + j]);

    for (int k0 = 0; k0 < KDIM; k0 += BK) {
        const bool from_agg = (k0 < HIDDEN);
        // --- A tile: 128x32 = 1024 float4, 512 thr x 2 ---
#pragma unroll
        for (int it = 0; it < 2; it++) {
            int slot = tid + it * GT;
            int r    = slot >> 3;        // 0..127
            int c4   = slot & 7;
            int m    = block_m + r;
            float4 v = make_float4(0.f, 0.f, 0.f, 0.f);
            if (m < N_NODES) {
                v = from_agg
                  ? *reinterpret_cast<const float4*>(&g_agg[m * HIDDEN + k0 + c4 * 4])
                  : *reinterpret_cast<const float4*>(&feat[m * HIDDEN + (k0 - HIDDEN) + c4 * 4]);
            }
            As[r][c4 * 4 + 0] = v.x;
            As[r][c4 * 4 + 1] = v.y;
            As[r][c4 * 4 + 2] = v.z;
            As[r][c4 * 4 + 3] = v.w;
        }
        // --- B tile: 32x128 = 1024 float4, 512 thr x 2 ---
#pragma unroll
        for (int it = 0; it < 2; it++) {
            int slot = tid + it * GT;
            int kk   = slot >> 5;
            int j4   = slot & 31;
            *reinterpret_cast<float4*>(&Bs[kk][j4 * 4]) =
                *reinterpret_cast<const float4*>(&g_Wt[(k0 + kk) * HIDDEN + j4 * 4]);
        }
        __syncthreads();

#pragma unroll
        for (int kk = 0; kk < BK; kk++) {
            float a_frag[TM];
#pragma unroll
            for (int i = 0; i < TM; i++) a_frag[i] = As[trow * TM + i][kk];
            float4 b0 = *reinterpret_cast<const float4*>(&Bs[kk][tcol * TN]);
            float4 b1 = *reinterpret_cast<const float4*>(&Bs[kk][tcol * TN + 4]);
            float b_frag[TN] = {b0.x, b0.y, b0.z, b0.w, b1.x, b1.y, b1.z, b1.w};
#pragma unroll
            for (int i = 0; i < TM; i++)
#pragma unroll
                for (int j = 0; j < TN; j++)
                    acc[i][j] += a_frag[i] * b_frag[j];
        }
        __syncthreads();
    }

#pragma unroll
    for (int i = 0; i < TM; i++) {
        int m = block_m + trow * TM + i;
        if (m < N_NODES) {
            float4 o0, o1;
            o0.x = acc[i][0] + bfrag[0];
            o0.y = acc[i][1] + bfrag[1];
            o0.z = acc[i][2] + bfrag[2];
            o0.w = acc[i][3] + bfrag[3];
            o1.x = acc[i][4] + bfrag[4];
            o1.y = acc[i][5] + bfrag[5];
            o1.z = acc[i][6] + bfrag[6];
            o1.w = acc[i][7] + bfrag[7];
            *reinterpret_cast<float4*>(&out[m * HIDDEN + tcol * TN])     = o0;
            *reinterpret_cast<float4*>(&out[m * HIDDEN + tcol * TN + 4]) = o1;
        }
    }
}

// ---------------- launcher --------------------------------------------------
extern "C" void kernel_launch(void* const* d_in, const int* in_sizes, int n_in,
                              void* d_out, int out_size) {
    const float* feat = nullptr;
    const void*  ei   = nullptr;
    const float* Wl   = nullptr;
    const float* bl   = nullptr;
    const float* Wr   = nullptr;
    for (int i = 0; i < n_in; i++) {
        int sz = in_sizes[i];
        if (sz == N_NODES * HIDDEN)      feat = (const float*)d_in[i];
        else if (sz == 2 * N_EDGES)      ei   = d_in[i];
        else if (sz == HIDDEN * HIDDEN) { if (!Wl) Wl = (const float*)d_in[i];
                                          else     Wr = (const float*)d_in[i]; }
        else if (sz == HIDDEN)           bl   = (const float*)d_in[i];
    }
    float* out = (float*)d_out;

    init_kernel<<<(KDIM * HIDDEN + 255) / 256, 256>>>(Wl, Wr, (const int*)ei);
    hist_kernel<<<(N_EDGES + 255) / 256, 256>>>(ei);
    partial_kernel<<<SCAN_NB, 256>>>();
    apply_kernel<<<SCAN_NB, 256>>>();
    place_kernel<<<(N_EDGES + 255) / 256, 256>>>(ei);
    gather_kernel<<<(N_NODES * 32 + 255) / 256, 256>>>(feat);
    gemm_kernel<<<(N_NODES + BM - 1) / BM, GT>>>(feat, bl, out);
}

// round 13
// speedup vs baseline: 1.1965x; 1.1965x over previous
#include <cuda_runtime.h>
#include <cuda_bf16.h>

#define N_NODES 20000
#define N_EDGES 640000
#define HIDDEN  128
#define KDIM    256   // concat [agg | x]

#define SCAN_NB    80
#define SCAN_CHUNK 250   // 80 * 250 = 20000 exactly

// ---------------- scratch (device globals; 16B-aligned) --------------------
__device__ __align__(16) float g_agg[N_NODES * HIDDEN];
__device__ __align__(16) float g_Wt[KDIM * HIDDEN];          // Wt[k][j]
__device__ int g_cnt[N_NODES];
__device__ int g_blocksum[SCAN_NB];
__device__ int g_rowstart[N_NODES + 1];
__device__ int g_wofs[N_NODES];
__device__ int g_srcidx[N_EDGES];
__device__ int g_is64;

__device__ __forceinline__ int load_idx(const void* ei, int pos) {
    if (g_is64) return (int)((const long long*)ei)[pos];
    return ((const int*)ei)[pos];
}

// ---------------- kernel 1: detect dtype + build Wt + zero counters --------
__global__ void init_kernel(const float* __restrict__ Wl,
                            const float* __restrict__ Wr,
                            const int* __restrict__ ei_raw) {
    int i = blockIdx.x * blockDim.x + threadIdx.x;
    if (i == 0) {
        int ok64 = 1;
#pragma unroll 1
        for (int k = 1; k < 256; k += 2) ok64 &= (ei_raw[k] == 0);
        g_is64 = ok64;
    }
    if (i < KDIM * HIDDEN) {
        int k = i >> 7;
        int j = i & 127;
        g_Wt[i] = (k < HIDDEN) ? Wl[j * HIDDEN + k]
                               : Wr[j * HIDDEN + (k - HIDDEN)];
    }
    if (i < N_NODES) g_cnt[i] = 0;
}

// ---------------- kernel 2: histogram of dst ------------------------------
__global__ void hist_kernel(const void* __restrict__ ei) {
    int e = blockIdx.x * blockDim.x + threadIdx.x;
    if (e >= N_EDGES) return;
    int d = load_idx(ei, N_EDGES + e);
    if ((unsigned)d < N_NODES) atomicAdd(&g_cnt[d], 1);
}

// ---------------- kernel 3a: per-block partial sums ------------------------
__global__ __launch_bounds__(256)
void partial_kernel() {
    __shared__ int sh[256];
    int t = threadIdx.x, b = blockIdx.x;
    int v = (t < SCAN_CHUNK) ? g_cnt[b * SCAN_CHUNK + t] : 0;
    sh[t] = v;
    __syncthreads();
#pragma unroll
    for (int o = 128; o > 0; o >>= 1) {
        if (t < o) sh[t] += sh[t + o];
        __syncthreads();
    }
    if (t == 0) g_blocksum[b] = sh[0];
}

// ---------------- kernel 3b: apply scan (exclusive offsets) ----------------
__global__ __launch_bounds__(256)
void apply_kernel() {
    __shared__ int sh[256];
    __shared__ int base_sh;
    int t = threadIdx.x, b = blockIdx.x;

    sh[t] = (t < b) ? g_blocksum[t] : 0;
    __syncthreads();
#pragma unroll
    for (int o = 128; o > 0; o >>= 1) {
        if (t < o) sh[t] += sh[t + o];
        __syncthreads();
    }
    if (t == 0) base_sh = sh[0];
    __syncthreads();
    int base = base_sh;

    int idx = b * SCAN_CHUNK + t;
    int v = (t < SCAN_CHUNK) ? g_cnt[idx] : 0;
    sh[t] = v;
    __syncthreads();
#pragma unroll
    for (int o = 1; o < 256; o <<= 1) {
        int x = sh[t];
        int add = (t >= o) ? sh[t - o] : 0;
        __syncthreads();
        sh[t] = x + add;
        __syncthreads();
    }
    int excl = base + sh[t] - v;
    if (t < SCAN_CHUNK) {
        g_rowstart[idx] = excl;
        g_wofs[idx]     = excl;
    }
    if (b == SCAN_NB - 1 && t == SCAN_CHUNK - 1)
        g_rowstart[N_NODES] = excl + v;
}

// ---------------- kernel 4: place src into CSR -----------------------------
__global__ void place_kernel(const void* __restrict__ ei) {
    int e = blockIdx.x * blockDim.x + threadIdx.x;
    if (e >= N_EDGES) return;
    int s = load_idx(ei, e);
    int d = load_idx(ei, N_EDGES + e);
    if ((unsigned)s >= N_NODES || (unsigned)d >= N_NODES) return;
    int pos = atomicAdd(&g_wofs[d], 1);
    g_srcidx[pos] = s;
}

// ---------------- kernel 5: atomic-free gather + mean ----------------------
__global__ void gather_kernel(const float* __restrict__ feat) {
    int gtid = blockIdx.x * blockDim.x + threadIdx.x;
    int nid  = gtid >> 5;
    int lane = gtid & 31;
    if (nid >= N_NODES) return;

    int beg = g_rowstart[nid];
    int end = g_rowstart[nid + 1];

    float4 acc = make_float4(0.f, 0.f, 0.f, 0.f);
    int i = beg;
#pragma unroll 1
    for (; i + 4 <= end; i += 4) {
        int s0 = g_srcidx[i + 0];
        int s1 = g_srcidx[i + 1];
        int s2 = g_srcidx[i + 2];
        int s3 = g_srcidx[i + 3];
        float4 v0 = *reinterpret_cast<const float4*>(&feat[s0 * HIDDEN + lane * 4]);
        float4 v1 = *reinterpret_cast<const float4*>(&feat[s1 * HIDDEN + lane * 4]);
        float4 v2 = *reinterpret_cast<const float4*>(&feat[s2 * HIDDEN + lane * 4]);
        float4 v3 = *reinterpret_cast<const float4*>(&feat[s3 * HIDDEN + lane * 4]);
        acc.x += v0.x + v1.x + v2.x + v3.x;
        acc.y += v0.y + v1.y + v2.y + v3.y;
        acc.z += v0.z + v1.z + v2.z + v3.z;
        acc.w += v0.w + v1.w + v2.w + v3.w;
    }
#pragma unroll 1
    for (; i < end; i++) {
        int s = g_srcidx[i];
        float4 v = *reinterpret_cast<const float4*>(&feat[s * HIDDEN + lane * 4]);
        acc.x += v.x; acc.y += v.y; acc.z += v.z; acc.w += v.w;
    }
    int deg = end - beg;
    float inv = 1.0f / (float)max(deg, 1);
    acc.x *= inv; acc.y *= inv; acc.z *= inv; acc.w *= inv;
    *reinterpret_cast<float4*>(&g_agg[nid * HIDDEN + lane * 4]) = acc;
}

// ---------------- kernel 6: fused SGEMM (256 thr, TM=8 — R5 measured) ------
// out[m][j] = sum_k A[m][k] * Wt[k][j] + b[j],  A = [agg | feat]
#define BM 128
#define BN 128
#define BK 32
#define TM 8
#define TN 8

__global__ __launch_bounds__(256)
void gemm_kernel(const float* __restrict__ feat,
                 const float* __restrict__ bias,
                 float* __restrict__ out) {
    __shared__ float As[BM][BK];
    __shared__ float Bs[BK][BN];

    const int tid     = threadIdx.x;
    const int block_m = blockIdx.x * BM;
    const int trow    = tid / 16;
    const int tcol    = tid % 16;

    float acc[TM][TN];
#pragma unroll
    for (int i = 0; i < TM; i++)
#pragma unroll
        for (int j = 0; j < TN; j++) acc[i][j] = 0.0f;

    float bfrag[TN];
#pragma unroll
    for (int j = 0; j < TN; j++) bfrag[j] = __ldg(&bias[tcol * TN + j]);

    for (int k0 = 0; k0 < KDIM; k0 += BK) {
        const bool from_agg = (k0 < HIDDEN);
#pragma unroll
        for (int it = 0; it < 4; it++) {
            int slot = tid + it * 256;
            int r    = slot >> 3;
            int c4   = slot & 7;
            int m    = block_m + r;
            float4 v = make_float4(0.f, 0.f, 0.f, 0.f);
            if (m < N_NODES) {
                v = from_agg
                  ? *reinterpret_cast<const float4*>(&g_agg[m * HIDDEN + k0 + c4 * 4])
                  : *reinterpret_cast<const float4*>(&feat[m * HIDDEN + (k0 - HIDDEN) + c4 * 4]);
            }
            *reinterpret_cast<float4*>(&As[r][c4 * 4]) = v;
        }
#pragma unroll
        for (int it = 0; it < 4; it++) {
            int slot = tid + it * 256;
            int kk   = slot >> 5;
            int j4   = slot & 31;
            *reinterpret_cast<float4*>(&Bs[kk][j4 * 4]) =
                *reinterpret_cast<const float4*>(&g_Wt[(k0 + kk) * HIDDEN + j4 * 4]);
        }
        __syncthreads();

#pragma unroll
        for (int kk = 0; kk < BK; kk++) {
            float a_frag[TM];
#pragma unroll
            for (int i = 0; i < TM; i++) a_frag[i] = As[trow * TM + i][kk];
            float4 b0 = *reinterpret_cast<const float4*>(&Bs[kk][tcol * TN]);
            float4 b1 = *reinterpret_cast<const float4*>(&Bs[kk][tcol * TN + 4]);
            float b_frag[TN] = {b0.x, b0.y, b0.z, b0.w, b1.x, b1.y, b1.z, b1.w};
#pragma unroll
            for (int i = 0; i < TM; i++)
#pragma unroll
                for (int j = 0; j < TN; j++)
                    acc[i][j] += a_frag[i] * b_frag[j];
        }
        __syncthreads();
    }

#pragma unroll
    for (int i = 0; i < TM; i++) {
        int m = block_m + trow * TM + i;
        if (m < N_NODES) {
            float4 o0, o1;
            o0.x = acc[i][0] + bfrag[0];
            o0.y = acc[i][1] + bfrag[1];
            o0.z = acc[i][2] + bfrag[2];
            o0.w = acc[i][3] + bfrag[3];
            o1.x = acc[i][4] + bfrag[4];
            o1.y = acc[i][5] + bfrag[5];
            o1.z = acc[i][6] + bfrag[6];
            o1.w = acc[i][7] + bfrag[7];
            *reinterpret_cast<float4*>(&out[m * HIDDEN + tcol * TN])     = o0;
            *reinterpret_cast<float4*>(&out[m * HIDDEN + tcol * TN + 4]) = o1;
        }
    }
}

// ---------------- launcher --------------------------------------------------
extern "C" void kernel_launch(void* const* d_in, const int* in_sizes, int n_in,
                              void* d_out, int out_size) {
    const float* feat = nullptr;
    const void*  ei   = nullptr;
    const float* Wl   = nullptr;
    const float* bl   = nullptr;
    const float* Wr   = nullptr;
    for (int i = 0; i < n_in; i++) {
        int sz = in_sizes[i];
        if (sz == N_NODES * HIDDEN)      feat = (const float*)d_in[i];
        else if (sz == 2 * N_EDGES)      ei   = d_in[i];
        else if (sz == HIDDEN * HIDDEN) { if (!Wl) Wl = (const float*)d_in[i];
                                          else     Wr = (const float*)d_in[i]; }
        else if (sz == HIDDEN)           bl   = (const float*)d_in[i];
    }
    float* out = (float*)d_out;

    init_kernel<<<(KDIM * HIDDEN + 255) / 256, 256>>>(Wl, Wr, (const int*)ei);
    hist_kernel<<<(N_EDGES + 255) / 256, 256>>>(ei);
    partial_kernel<<<SCAN_NB, 256>>>();
    apply_kernel<<<SCAN_NB, 256>>>();
    place_kernel<<<(N_EDGES + 255) / 256, 256>>>(ei);
    gather_kernel<<<(N_NODES * 32 + 255) / 256, 256>>>(feat);
    gemm_kernel<<<(N_NODES + BM - 1) / BM, 256>>>(feat, bl, out);
}

// round 16
// speedup vs baseline: 1.5002x; 1.2538x over previous
#include <cuda_runtime.h>
#include <cuda_bf16.h>
#include <cstdint>

#define N_NODES 20000
#define N_EDGES 640000
#define HIDDEN  128
#define KDIM    256   // concat [agg | x]

#define SCAN_NB    80
#define SCAN_CHUNK 250   // 80 * 250 = 20000 exactly

// ---------------- scratch (device globals; 16B-aligned) --------------------
__device__ __align__(16) float g_agg[N_NODES * HIDDEN];
__device__ __align__(16) __nv_bfloat16 g_Whi[HIDDEN * KDIM];   // [n=j][k]
__device__ __align__(16) __nv_bfloat16 g_Wlo[HIDDEN * KDIM];   // [n=j][k]
__device__ int g_cnt[N_NODES];
__device__ int g_blocksum[SCAN_NB];
__device__ int g_rowstart[N_NODES + 1];
__device__ int g_wofs[N_NODES];
__device__ int g_srcidx[N_EDGES];
__device__ int g_is64;

__device__ __forceinline__ int load_idx(const void* ei, int pos) {
    // little-endian: low word of int64 == the id (ids < 2^31)
    if (g_is64) return ((const int*)ei)[2 * pos];
    return ((const int*)ei)[pos];
}

__device__ __forceinline__ void split1(float x, __nv_bfloat16& h, __nv_bfloat16& l) {
    h = __float2bfloat16_rn(x);
    l = __float2bfloat16_rn(x - __bfloat162float(h));
}

__device__ __forceinline__ void split2(float x0, float x1, uint32_t& hp, uint32_t& lp) {
    __nv_bfloat16 h0, l0, h1, l1;
    split1(x0, h0, l0);
    split1(x1, h1, l1);
    hp = (uint32_t)__bfloat16_as_ushort(h0) | ((uint32_t)__bfloat16_as_ushort(h1) << 16);
    lp = (uint32_t)__bfloat16_as_ushort(l0) | ((uint32_t)__bfloat16_as_ushort(l1) << 16);
}

// ---------------- kernel 1: detect dtype + split W + zero counters ---------
// grid covers HIDDEN*KDIM = 32768 threads
__global__ void init_kernel(const float* __restrict__ Wl,
                            const float* __restrict__ Wr,
                            const int* __restrict__ ei_raw) {
    int i = blockIdx.x * blockDim.x + threadIdx.x;
    if (i == 0) {
        int ok64 = 1;
#pragma unroll 1
        for (int k = 1; k < 256; k += 2) ok64 &= (ei_raw[k] == 0);
        g_is64 = ok64;
    }
    if (i < HIDDEN * KDIM) {
        int j = i >> 8;        // output col (n)
        int k = i & 255;       // reduction dim
        float val = (k < HIDDEN) ? Wl[j * HIDDEN + k]
                                 : Wr[j * HIDDEN + (k - HIDDEN)];
        __nv_bfloat16 h, l;
        split1(val, h, l);
        g_Whi[i] = h;          // i == j*KDIM + k  -> [n][k] layout
        g_Wlo[i] = l;
    }
    if (i < N_NODES) g_cnt[i] = 0;
}

// ---------------- kernel 2: histogram of dst ------------------------------
__global__ void hist_kernel(const void* __restrict__ ei) {
    int e = blockIdx.x * blockDim.x + threadIdx.x;
    if (e >= N_EDGES) return;
    int d = load_idx(ei, N_EDGES + e);
    if ((unsigned)d < N_NODES) atomicAdd(&g_cnt[d], 1);
}

// ---------------- kernel 3a: per-block partial sums ------------------------
__global__ __launch_bounds__(256)
void partial_kernel() {
    __shared__ int sh[256];
    int t = threadIdx.x, b = blockIdx.x;
    int v = (t < SCAN_CHUNK) ? g_cnt[b * SCAN_CHUNK + t] : 0;
    sh[t] = v;
    __syncthreads();
#pragma unroll
    for (int o = 128; o > 0; o >>= 1) {
        if (t < o) sh[t] += sh[t + o];
        __syncthreads();
    }
    if (t == 0) g_blocksum[b] = sh[0];
}

// ---------------- kernel 3b: apply scan (exclusive offsets) ----------------
__global__ __launch_bounds__(256)
void apply_kernel() {
    __shared__ int sh[256];
    __shared__ int base_sh;
    int t = threadIdx.x, b = blockIdx.x;

    sh[t] = (t < b) ? g_blocksum[t] : 0;
    __syncthreads();
#pragma unroll
    for (int o = 128; o > 0; o >>= 1) {
        if (t < o) sh[t] += sh[t + o];
        __syncthreads();
    }
    if (t == 0) base_sh = sh[0];
    __syncthreads();
    int base = base_sh;

    int idx = b * SCAN_CHUNK + t;
    int v = (t < SCAN_CHUNK) ? g_cnt[idx] : 0;
    sh[t] = v;
    __syncthreads();
#pragma unroll
    for (int o = 1; o < 256; o <<= 1) {
        int x = sh[t];
        int add = (t >= o) ? sh[t - o] : 0;
        __syncthreads();
        sh[t] = x + add;
        __syncthreads();
    }
    int excl = base + sh[t] - v;
    if (t < SCAN_CHUNK) {
        g_rowstart[idx] = excl;
        g_wofs[idx]     = excl;
    }
    if (b == SCAN_NB - 1 && t == SCAN_CHUNK - 1)
        g_rowstart[N_NODES] = excl + v;
}

// ---------------- kernel 4: place src into CSR -----------------------------
__global__ void place_kernel(const void* __restrict__ ei) {
    int e = blockIdx.x * blockDim.x + threadIdx.x;
    if (e >= N_EDGES) return;
    int s = load_idx(ei, e);
    int d = load_idx(ei, N_EDGES + e);
    if ((unsigned)s >= N_NODES || (unsigned)d >= N_NODES) return;
    int pos = atomicAdd(&g_wofs[d], 1);
    g_srcidx[pos] = s;
}

// ---------------- kernel 5: atomic-free gather + mean ----------------------
__global__ void gather_kernel(const float* __restrict__ feat) {
    int gtid = blockIdx.x * blockDim.x + threadIdx.x;
    int nid  = gtid >> 5;
    int lane = gtid & 31;
    if (nid >= N_NODES) return;

    int beg = g_rowstart[nid];
    int end = g_rowstart[nid + 1];

    float4 acc = make_float4(0.f, 0.f, 0.f, 0.f);
    int i = beg;
#pragma unroll 1
    for (; i + 4 <= end; i += 4) {
        int s0 = g_srcidx[i + 0];
        int s1 = g_srcidx[i + 1];
        int s2 = g_srcidx[i + 2];
        int s3 = g_srcidx[i + 3];
        float4 v0 = *reinterpret_cast<const float4*>(&feat[s0 * HIDDEN + lane * 4]);
        float4 v1 = *reinterpret_cast<const float4*>(&feat[s1 * HIDDEN + lane * 4]);
        float4 v2 = *reinterpret_cast<const float4*>(&feat[s2 * HIDDEN + lane * 4]);
        float4 v3 = *reinterpret_cast<const float4*>(&feat[s3 * HIDDEN + lane * 4]);
        acc.x += v0.x + v1.x + v2.x + v3.x;
        acc.y += v0.y + v1.y + v2.y + v3.y;
        acc.z += v0.z + v1.z + v2.z + v3.z;
        acc.w += v0.w + v1.w + v2.w + v3.w;
    }
#pragma unroll 1
    for (; i < end; i++) {
        int s = g_srcidx[i];
        float4 v = *reinterpret_cast<const float4*>(&feat[s * HIDDEN + lane * 4]);
        acc.x += v.x; acc.y += v.y; acc.z += v.z; acc.w += v.w;
    }
    int deg = end - beg;
    float inv = 1.0f / (float)max(deg, 1);
    acc.x *= inv; acc.y *= inv; acc.z *= inv; acc.w *= inv;
    *reinterpret_cast<float4*>(&g_agg[nid * HIDDEN + lane * 4]) = acc;
}

// ---------------- kernel 6: split-bf16 tensor-core GEMM --------------------
// out[m][j] = sum_k A[m][k]*W[j][k] + b[j],  A = [agg | feat] (m x 256)
// D += Ah*Bh + Ah*Bl + Al*Bh  (lo*lo dropped, ~2^-16 relative)
// block: 128 rows x all 128 cols, 256 threads = 8 warps (2 m x 4 n)
// warp tile: 64m x 32n = 4 mfrag(16) x 4 nfrag(8); mma.m16n8k16
#define GBM 128
#define ASTRIDE 20   // u32 per row (16 data + 4 pad) -> conflict-free frags

__device__ __forceinline__ void mma_bf16(float* d, const uint32_t* a,
                                         uint32_t b0, uint32_t b1) {
    asm volatile(
        "mma.sync.aligned.m16n8k16.row.col.f32.bf16.bf16.f32 "
        "{%0,%1,%2,%3}, {%4,%5,%6,%7}, {%8,%9}, {%0,%1,%2,%3};"
        : "+f"(d[0]), "+f"(d[1]), "+f"(d[2]), "+f"(d[3])
        : "r"(a[0]), "r"(a[1]), "r"(a[2]), "r"(a[3]), "r"(b0), "r"(b1));
}

__global__ __launch_bounds__(256)
void gemm_kernel(const float* __restrict__ feat,
                 const float* __restrict__ bias,
                 float* __restrict__ out) {
    __shared__ uint32_t Ahi[GBM * ASTRIDE];   // bf16x2 pairs along k
    __shared__ uint32_t Alo[GBM * ASTRIDE];

    const int tid    = threadIdx.x;
    const int lane   = tid & 31;
    const int wid    = tid >> 5;
    const int warp_m = (wid & 1) * 64;
    const int warp_n = (wid >> 1) * 32;
    const int block_m = blockIdx.x * GBM;

    float acc[4][4][4];
#pragma unroll
    for (int mf = 0; mf < 4; mf++)
#pragma unroll
        for (int nf = 0; nf < 4; nf++)
#pragma unroll
            for (int r = 0; r < 4; r++) acc[mf][nf][r] = 0.0f;

    const int gq = lane >> 2;   // 0..7
    const int gr = lane & 3;    // 0..3

    for (int chunk = 0; chunk < 8; chunk++) {
        int k0 = chunk * 32;
        const bool from_agg = (k0 < HIDDEN);
        // ---- load + split A tile: 128 x 32 f32 = 1024 float4 ----
#pragma unroll
        for (int it = 0; it < 4; it++) {
            int slot = tid + it * 256;
            int r    = slot >> 3;
            int c4   = slot & 7;
            int m    = block_m + r;
            float4 v = make_float4(0.f, 0.f, 0.f, 0.f);
            if (m < N_NODES) {
                v = from_agg
                  ? *reinterpret_cast<const float4*>(&g_agg[m * HIDDEN + k0 + c4 * 4])
                  : *reinterpret_cast<const float4*>(&feat[m * HIDDEN + (k0 - HIDDEN) + c4 * 4]);
            }
            uint32_t h01, l01, h23, l23;
            split2(v.x, v.y, h01, l01);
            split2(v.z, v.w, h23, l23);
            Ahi[r * ASTRIDE + c4 * 2 + 0] = h01;
            Ahi[r * ASTRIDE + c4 * 2 + 1] = h23;
            Alo[r * ASTRIDE + c4 * 2 + 0] = l01;
            Alo[r * ASTRIDE + c4 * 2 + 1] = l23;
        }
        __syncthreads();

#pragma unroll
        for (int ks = 0; ks < 2; ks++) {
            const int kg = k0 + ks * 16;          // global k of this 16-step
            const int cu = ks * 8 + gr;           // u32 col for a0

            // A fragments for 4 m-tiles
            uint32_t ah[4][4], al[4][4];
#pragma unroll
            for (int mf = 0; mf < 4; mf++) {
                int r0 = warp_m + mf * 16 + gq;
                ah[mf][0] = Ahi[r0 * ASTRIDE + cu];
                ah[mf][1] = Ahi[(r0 + 8) * ASTRIDE + cu];
                ah[mf][2] = Ahi[r0 * ASTRIDE + cu + 4];
                ah[mf][3] = Ahi[(r0 + 8) * ASTRIDE + cu + 4];
                al[mf][0] = Alo[r0 * ASTRIDE + cu];
                al[mf][1] = Alo[(r0 + 8) * ASTRIDE + cu];
                al[mf][2] = Alo[r0 * ASTRIDE + cu + 4];
                al[mf][3] = Alo[(r0 + 8) * ASTRIDE + cu + 4];
            }

            // B fragments straight from (L1/L2-hot) global, then MMA
#pragma unroll
            for (int nf = 0; nf < 4; nf++) {
                int n  = warp_n + nf * 8 + gq;
                int kk = kg + gr * 2;
                uint32_t bh0 = *reinterpret_cast<const uint32_t*>(&g_Whi[n * KDIM + kk]);
                uint32_t bh1 = *reinterpret_cast<const uint32_t*>(&g_Whi[n * KDIM + kk + 8]);
                uint32_t bl0 = *reinterpret_cast<const uint32_t*>(&g_Wlo[n * KDIM + kk]);
                uint32_t bl1 = *reinterpret_cast<const uint32_t*>(&g_Wlo[n * KDIM + kk + 8]);
#pragma unroll
                for (int mf = 0; mf < 4; mf++) {
                    mma_bf16(acc[mf][nf], ah[mf], bh0, bh1);
                    mma_bf16(acc[mf][nf], ah[mf], bl0, bl1);
                    mma_bf16(acc[mf][nf], al[mf], bh0, bh1);
                }
            }
        }
        __syncthreads();
    }

    // ---- epilogue: bias + store (float2 per d-pair) ----
#pragma unroll
    for (int nf = 0; nf < 4; nf++) {
        int j = warp_n + nf * 8 + gr * 2;
        float2 b2 = *reinterpret_cast<const float2*>(&bias[j]);
#pragma unroll
        for (int mf = 0; mf < 4; mf++) {
            int r0 = block_m + warp_m + mf * 16 + gq;
            if (r0 < N_NODES) {
                float2 o = make_float2(acc[mf][nf][0] + b2.x, acc[mf][nf][1] + b2.y);
                *reinterpret_cast<float2*>(&out[r0 * HIDDEN + j]) = o;
            }
            int r1 = r0 + 8;
            if (r1 < N_NODES) {
                float2 o = make_float2(acc[mf][nf][2] + b2.x, acc[mf][nf][3] + b2.y);
                *reinterpret_cast<float2*>(&out[r1 * HIDDEN + j]) = o;
            }
        }
    }
}

// ---------------- launcher --------------------------------------------------
extern "C" void kernel_launch(void* const* d_in, const int* in_sizes, int n_in,
                              void* d_out, int out_size) {
    const float* feat = nullptr;
    const void*  ei   = nullptr;
    const float* Wl   = nullptr;
    const float* bl   = nullptr;
    const float* Wr   = nullptr;
    for (int i = 0; i < n_in; i++) {
        int sz = in_sizes[i];
        if (sz == N_NODES * HIDDEN)      feat = (const float*)d_in[i];
        else if (sz == 2 * N_EDGES)      ei   = d_in[i];
        else if (sz == HIDDEN * HIDDEN) { if (!Wl) Wl = (const float*)d_in[i];
                                          else     Wr = (const float*)d_in[i]; }
        else if (sz == HIDDEN)           bl   = (const float*)d_in[i];
    }
    float* out = (float*)d_out;

    init_kernel<<<(HIDDEN * KDIM + 255) / 256, 256>>>(Wl, Wr, (const int*)ei);
    hist_kernel<<<(N_EDGES + 255) / 256, 256>>>(ei);
    partial_kernel<<<SCAN_NB, 256>>>();
    apply_kernel<<<SCAN_NB, 256>>>();
    place_kernel<<<(N_EDGES + 255) / 256, 256>>>(ei);
    gather_kernel<<<(N_NODES * 32 + 255) / 256, 256>>>(feat);
    gemm_kernel<<<(N_NODES + GBM - 1) / GBM, 256>>>(feat, bl, out);
}